// round 1
// baseline (speedup 1.0000x reference)
#include <cuda_runtime.h>
#include <math.h>

#define H 128
#define KVDIM 256
#define NMAX 50000
#define EMAX 500000
#define GPAD 132

// ---------------- scratch (device globals; no allocations allowed) ----------
__device__ float    g_hq[NMAX * H];        // h @ Wq + bq           (per node)
__device__ float    g_hkv[NMAX * KVDIM];   // h @ Wkv[9:,:] + bkv   (per node)
__device__ float    g_v[EMAX * H];         // v per edge
__device__ float    g_cd[EMAX * 9];        // coord_diff per edge
__device__ float    g_araw[EMAX];          // raw attention logits
__device__ float    g_ex[EMAX];            // exp(logit - max)
__device__ unsigned g_maxbits[NMAX];       // segment max (monotone uint key)
__device__ float    g_den[NMAX];           // softmax denominator
__device__ float    g_agg[NMAX * H];       // sum alpha*v
__device__ float    g_cagg[NMAX * 9];      // sum trans

// ---------------- helpers ----------------------------------------------------
__device__ __forceinline__ unsigned fkey(float x) {
    unsigned b = __float_as_uint(x);
    return (b & 0x80000000u) ? ~b : (b | 0x80000000u);
}
__device__ __forceinline__ float fdec(unsigned u) {
    unsigned b = (u & 0x80000000u) ? (u & 0x7fffffffu) : ~u;
    return __uint_as_float(b);
}
__device__ __forceinline__ unsigned long long pack2(float x, float y) {
    unsigned long long r;
    asm("mov.b64 %0, {%1, %2};" : "=l"(r) : "f"(x), "f"(y));
    return r;
}
__device__ __forceinline__ void fma2(unsigned long long& d, unsigned long long a,
                                     unsigned long long b) {
    asm("fma.rn.f32x2 %0, %1, %2, %0;" : "+l"(d) : "l"(a), "l"(b));
}
__device__ __forceinline__ float lo32(unsigned long long v) {
    return __uint_as_float((unsigned)v);
}
__device__ __forceinline__ float hi32(unsigned long long v) {
    return __uint_as_float((unsigned)(v >> 32));
}

// ---------------- K0: init scratch -------------------------------------------
__global__ void init_kernel(int N) {
    int i = blockIdx.x * blockDim.x + threadIdx.x;
    if (i < N * H) g_agg[i] = 0.f;
    if (i < N * 9) g_cagg[i] = 0.f;
    if (i < N) {
        g_den[i] = 0.f;
        g_maxbits[i] = 0x007FFFFFu;  // fkey(-inf)
    }
}

// ---------------- K1/K2: node GEMM  C(N x M) = A(N x 128) @ B + bias ---------
__global__ __launch_bounds__(256, 2) void node_gemm(
    const float* __restrict__ A, const float* __restrict__ B, int ldb,
    const float* __restrict__ bias, float* __restrict__ C, int ldc, int N) {
    extern __shared__ float smem[];
    float* As = smem;               // [128][GPAD]
    float* Ws = smem + 128 * GPAD;  // [32][GPAD]
    int tid = threadIdx.x;
    int tx = tid & 15, ty = tid >> 4;
    int n0 = blockIdx.x * 128;
    int nt = blockIdx.y * 128;

#pragma unroll
    for (int it = 0; it < 16; it++) {
        int t4 = tid + 256 * it;
        int er = t4 >> 5, cf = t4 & 31;
        int r = n0 + er;
        float4 f = (r < N) ? *((const float4*)A + (size_t)r * 32 + cf)
                           : make_float4(0.f, 0.f, 0.f, 0.f);
        *(float4*)&As[er * GPAD + cf * 4] = f;
    }

    unsigned long long acc[8][4];
#pragma unroll
    for (int i = 0; i < 8; i++)
#pragma unroll
        for (int j = 0; j < 4; j++) acc[i][j] = 0ull;

    for (int k0 = 0; k0 < 128; k0 += 32) {
        __syncthreads();
#pragma unroll
        for (int it = 0; it < 4; it++) {
            int t4 = tid + 256 * it;
            int kk = t4 >> 5, cf = t4 & 31;
            float4 f = *(const float4*)&B[(size_t)(k0 + kk) * ldb + nt + cf * 4];
            *(float4*)&Ws[kk * GPAD + cf * 4] = f;
        }
        __syncthreads();
#pragma unroll 4
        for (int kk = 0; kk < 32; kk++) {
            ulonglong2 wa = *(const ulonglong2*)&Ws[kk * GPAD + tx * 8];
            ulonglong2 wb = *(const ulonglong2*)&Ws[kk * GPAD + tx * 8 + 4];
#pragma unroll
            for (int i = 0; i < 8; i++) {
                float v = As[(ty * 8 + i) * GPAD + k0 + kk];
                unsigned long long v2 = pack2(v, v);
                fma2(acc[i][0], v2, wa.x);
                fma2(acc[i][1], v2, wa.y);
                fma2(acc[i][2], v2, wb.x);
                fma2(acc[i][3], v2, wb.y);
            }
        }
    }
#pragma unroll
    for (int i = 0; i < 8; i++) {
        int r = n0 + ty * 8 + i;
        if (r >= N) continue;
#pragma unroll
        for (int j = 0; j < 4; j++) {
            int n = nt + tx * 8 + 2 * j;
            float lov = lo32(acc[i][j]) + bias[n];
            float hiv = hi32(acc[i][j]) + bias[n + 1];
            *(float2*)&C[(size_t)r * ldc + n] = make_float2(lov, hiv);
        }
    }
}

// ---------------- K3: per-edge kv / k / v / alpha_raw (warp per edge) --------
__global__ void edge_kv_kernel(const float* __restrict__ coord,
                               const int* __restrict__ row,
                               const int* __restrict__ col,
                               const float* __restrict__ Wkv, int E) {
    int gw = (int)((blockIdx.x * blockDim.x + threadIdx.x) >> 5);
    int lane = threadIdx.x & 31;
    if (gw >= E) return;
    int r = row[gw], c = col[gw];

    float cd[9];
#pragma unroll
    for (int i = 0; i < 9; i++)
        cd[i] = coord[(size_t)r * 9 + i] - coord[(size_t)c * 9 + i];
    float rad[9];
#pragma unroll
    for (int i = 0; i < 3; i++)
#pragma unroll
        for (int j = 0; j < 3; j++)
            rad[i * 3 + j] = cd[i * 3] * cd[j * 3] + cd[i * 3 + 1] * cd[j * 3 + 1] +
                             cd[i * 3 + 2] * cd[j * 3 + 2];
    if (lane < 9) g_cd[(size_t)gw * 9 + lane] = cd[lane];

    const float2* hkvc = (const float2*)(g_hkv + (size_t)c * KVDIM);
    const float2* Wkv2 = (const float2*)Wkv;
    float ap = 0.f;
#pragma unroll
    for (int t = 0; t < 4; t++) {
        int m = lane + 32 * t;
        float2 kv = hkvc[m];
#pragma unroll
        for (int i = 0; i < 9; i++) {
            float2 w = Wkv2[i * 128 + m];
            kv.x += rad[i] * w.x;
            kv.y += rad[i] * w.y;
        }
        g_v[(size_t)gw * H + m] = kv.y;
        ap += g_hq[(size_t)r * H + m] * kv.x;
    }
#pragma unroll
    for (int o = 16; o; o >>= 1) ap += __shfl_xor_sync(0xffffffffu, ap, o);
    if (lane == 0) {
        g_araw[gw] = ap;
        atomicMax(&g_maxbits[r], fkey(ap));
    }
}

// ---------------- K4: softmax numerator/denominator --------------------------
__global__ void softmax_den_kernel(const int* __restrict__ row, int E) {
    int e = blockIdx.x * blockDim.x + threadIdx.x;
    if (e >= E) return;
    int r = row[e];
    float amax = fdec(g_maxbits[r]);
    float ex = expf(g_araw[e] - amax);
    g_ex[e] = ex;
    atomicAdd(&g_den[r], ex);
}

// ---------------- K5: heavy fused kernel -------------------------------------
// per 128-edge tile: U = silu(V @ Wc1), cv = U @ Wc2, coord_v = alpha*cv,
// scatter cagg, scatter agg += alpha*v, write alpha output.
__global__ __launch_bounds__(256, 2) void heavy_kernel(
    const float* __restrict__ Wc1, const float* __restrict__ Wc2,
    const int* __restrict__ row, float* __restrict__ alpha_out, int E) {
    extern __shared__ float smem[];
    float* Vs = smem;                            // [128][GPAD]
    float* Ws = smem + 128 * GPAD;               // [32][GPAD]
    float* cv_s = smem + 128 * GPAD + 32 * GPAD; // [128*3]
    float* alpha_s = cv_s + 384;                 // [128]
    int* row_s = (int*)(alpha_s + 128);          // [128]

    int tid = threadIdx.x;
    int tx = tid & 15, ty = tid >> 4;
    int e0 = blockIdx.x * 128;

#pragma unroll
    for (int it = 0; it < 16; it++) {
        int t4 = tid + 256 * it;
        int er = t4 >> 5, cf = t4 & 31;
        int e = e0 + er;
        float4 f = (e < E) ? *((const float4*)g_v + (size_t)e * 32 + cf)
                           : make_float4(0.f, 0.f, 0.f, 0.f);
        *(float4*)&Vs[er * GPAD + cf * 4] = f;
    }
    if (tid < 128) {
        int e = e0 + tid;
        if (e < E) {
            int r = row[e];
            row_s[tid] = r;
            alpha_s[tid] = g_ex[e] / g_den[r];
        } else {
            row_s[tid] = -1;
            alpha_s[tid] = 0.f;
        }
    }
    for (int i = tid; i < 384; i += 256) cv_s[i] = 0.f;

    for (int chunk = 0; chunk < 4; chunk++) {
        unsigned long long acc[8][4];
#pragma unroll
        for (int i = 0; i < 8; i++)
#pragma unroll
            for (int j = 0; j < 4; j++) acc[i][j] = 0ull;

        for (int k0 = 0; k0 < 128; k0 += 32) {
            __syncthreads();
#pragma unroll
            for (int it = 0; it < 4; it++) {
                int t4 = tid + 256 * it;
                int kk = t4 >> 5, cf = t4 & 31;
                float4 f = *(const float4*)&Wc1[(size_t)(k0 + kk) * 512 +
                                                chunk * 128 + cf * 4];
                *(float4*)&Ws[kk * GPAD + cf * 4] = f;
            }
            __syncthreads();
#pragma unroll 4
            for (int kk = 0; kk < 32; kk++) {
                ulonglong2 wa = *(const ulonglong2*)&Ws[kk * GPAD + tx * 8];
                ulonglong2 wb = *(const ulonglong2*)&Ws[kk * GPAD + tx * 8 + 4];
#pragma unroll
                for (int i = 0; i < 8; i++) {
                    float v = Vs[(ty * 8 + i) * GPAD + k0 + kk];
                    unsigned long long v2 = pack2(v, v);
                    fma2(acc[i][0], v2, wa.x);
                    fma2(acc[i][1], v2, wa.y);
                    fma2(acc[i][2], v2, wb.x);
                    fma2(acc[i][3], v2, wb.y);
                }
            }
        }
        // epilogue: silu, fold Wc2, accumulate per-edge cv partials
#pragma unroll
        for (int i = 0; i < 8; i++) {
            float p0 = 0.f, p1 = 0.f, p2 = 0.f;
#pragma unroll
            for (int j = 0; j < 4; j++) {
                int n = chunk * 128 + tx * 8 + 2 * j;
                float x0 = lo32(acc[i][j]);
                float x1 = hi32(acc[i][j]);
                float u0 = x0 / (1.f + __expf(-x0));
                float u1 = x1 / (1.f + __expf(-x1));
                p0 += u0 * Wc2[n * 3 + 0] + u1 * Wc2[n * 3 + 3];
                p1 += u0 * Wc2[n * 3 + 1] + u1 * Wc2[n * 3 + 4];
                p2 += u0 * Wc2[n * 3 + 2] + u1 * Wc2[n * 3 + 5];
            }
            int er = ty * 8 + i;
            atomicAdd(&cv_s[er * 3 + 0], p0);
            atomicAdd(&cv_s[er * 3 + 1], p1);
            atomicAdd(&cv_s[er * 3 + 2], p2);
        }
    }
    __syncthreads();

    if (tid < 128) {
        int e = e0 + tid;
        if (e < E) {
            float a = alpha_s[tid];
            alpha_out[e] = a;
            int r = row_s[tid];
            float c0 = cv_s[tid * 3 + 0] * a;
            float c1 = cv_s[tid * 3 + 1] * a;
            float c2 = cv_s[tid * 3 + 2] * a;
#pragma unroll
            for (int d = 0; d < 3; d++) {
                atomicAdd(&g_cagg[r * 9 + d], g_cd[(size_t)e * 9 + d] * c0);
                atomicAdd(&g_cagg[r * 9 + 3 + d], g_cd[(size_t)e * 9 + 3 + d] * c1);
                atomicAdd(&g_cagg[r * 9 + 6 + d], g_cd[(size_t)e * 9 + 6 + d] * c2);
            }
        }
    }
    // agg += alpha * v
    for (int idx = tid; idx < 128 * H; idx += 256) {
        int er = idx >> 7, k = idx & 127;
        int r = row_s[er];
        if (r >= 0)
            atomicAdd(&g_agg[(size_t)r * H + k], alpha_s[er] * Vs[er * GPAD + k]);
    }
}

// ---------------- K6: finalize outputs ---------------------------------------
__global__ void finalize_kernel(const float* __restrict__ h,
                                const float* __restrict__ coord,
                                float* __restrict__ out, int N) {
    int i = blockIdx.x * blockDim.x + threadIdx.x;
    int nh = N * H;
    if (i < nh) {
        out[i] = h[i] + g_agg[i];
    } else {
        int j = i - nh;
        if (j < N * 9) {
            float cg = g_cagg[j];
            cg = fminf(fmaxf(cg, -10.f), 10.f);
            out[nh + j] = coord[j] + cg;
        }
    }
}

// ---------------- launch ------------------------------------------------------
extern "C" void kernel_launch(void* const* d_in, const int* in_sizes, int n_in,
                              void* d_out, int out_size) {
    const float* h = (const float*)d_in[0];
    const float* coord = (const float*)d_in[1];
    const int* row = (const int*)d_in[2];
    const int* col = (const int*)d_in[3];
    const float* Wq = (const float*)d_in[4];
    const float* bq = (const float*)d_in[5];
    const float* Wkv = (const float*)d_in[6];
    const float* bkv = (const float*)d_in[7];
    const float* Wc1 = (const float*)d_in[8];
    const float* Wc2 = (const float*)d_in[9];
    int N = in_sizes[0] / H;
    int E = in_sizes[2];
    float* out = (float*)d_out;

    size_t smem_g = (size_t)(128 * GPAD + 32 * GPAD) * sizeof(float);
    size_t smem_h = smem_g + (size_t)(384 + 128 + 128) * sizeof(float);
    cudaFuncSetAttribute((const void*)node_gemm,
                         cudaFuncAttributeMaxDynamicSharedMemorySize, (int)smem_h);
    cudaFuncSetAttribute((const void*)heavy_kernel,
                         cudaFuncAttributeMaxDynamicSharedMemorySize, (int)smem_h);

    float *hq_p, *hkv_p;
    cudaGetSymbolAddress((void**)&hq_p, g_hq);
    cudaGetSymbolAddress((void**)&hkv_p, g_hkv);

    init_kernel<<<(N * H + 255) / 256, 256>>>(N);

    dim3 gq((N + 127) / 128, 1);
    node_gemm<<<gq, 256, smem_g>>>(h, Wq, H, bq, hq_p, H, N);
    dim3 gkv((N + 127) / 128, 2);
    node_gemm<<<gkv, 256, smem_g>>>(h, Wkv + 9 * KVDIM, KVDIM, bkv, hkv_p, KVDIM, N);

    edge_kv_kernel<<<(E + 7) / 8, 256>>>(coord, row, col, Wkv, E);
    softmax_den_kernel<<<(E + 255) / 256, 256>>>(row, E);

    heavy_kernel<<<(E + 127) / 128, 256, smem_h>>>(
        Wc1, Wc2, row, out + (size_t)N * H + (size_t)N * 9, E);

    finalize_kernel<<<(N * H + N * 9 + 255) / 256, 256>>>(h, coord, out, N);
}

// round 2
// speedup vs baseline: 3.4934x; 3.4934x over previous
#include <cuda_runtime.h>
#include <math.h>

#define H 128
#define KVDIM 256
#define ZDIM 512
#define NMAX 50000
#define EMAX 500000
#define GPAD 132

// ---------------- scratch (device globals) -----------------------------------
__device__ float    g_hq[NMAX * H];
__device__ float    g_hk[NMAX * H];
__device__ float    g_hv[NMAX * H];
__device__ float    g_Z[NMAX * ZDIM];     // (h @ Whz + bz)  == hv @ Wc1
__device__ float    g_P[NMAX * 9];        // hq . Wk_rad rows
__device__ float    g_cd[EMAX * 9];
__device__ float    g_araw[EMAX];
__device__ float    g_ex[EMAX];
__device__ unsigned g_maxbits[NMAX];
__device__ float    g_den[NMAX];
__device__ float    g_agg[NMAX * H];
__device__ float    g_cagg[NMAX * 9];
// folded weights
__device__ float    g_wkh[H * H];         // Wkv[9+t][2m]
__device__ float    g_wvh[H * H];         // Wkv[9+t][2m+1]
__device__ float    g_wkr[9 * H];         // Wkv[i][2m]
__device__ float    g_wvr[9 * H];         // Wkv[i][2m+1]
__device__ float    g_bk[H];
__device__ float    g_bv[H];
__device__ float    g_whz[H * ZDIM];      // Wvh @ Wc1
__device__ float    g_wvc1[9 * ZDIM];     // Wvr @ Wc1
__device__ float    g_bz[ZDIM];           // bv @ Wc1

// ---------------- helpers -----------------------------------------------------
__device__ __forceinline__ unsigned fkey(float x) {
    unsigned b = __float_as_uint(x);
    return (b & 0x80000000u) ? ~b : (b | 0x80000000u);
}
__device__ __forceinline__ float fdec(unsigned u) {
    unsigned b = (u & 0x80000000u) ? (u & 0x7fffffffu) : ~u;
    return __uint_as_float(b);
}
__device__ __forceinline__ unsigned long long pack2(float x, float y) {
    unsigned long long r;
    asm("mov.b64 %0, {%1, %2};" : "=l"(r) : "f"(x), "f"(y));
    return r;
}
__device__ __forceinline__ void fma2(unsigned long long& d, unsigned long long a,
                                     unsigned long long b) {
    asm("fma.rn.f32x2 %0, %1, %2, %0;" : "+l"(d) : "l"(a), "l"(b));
}
__device__ __forceinline__ float lo32(unsigned long long v) {
    return __uint_as_float((unsigned)v);
}
__device__ __forceinline__ float hi32(unsigned long long v) {
    return __uint_as_float((unsigned)(v >> 32));
}

// ---------------- K0: init ----------------------------------------------------
__global__ void init_kernel(int N) {
    int i = blockIdx.x * blockDim.x + threadIdx.x;
    if (i < N * H) g_agg[i] = 0.f;
    if (i < N * 9) g_cagg[i] = 0.f;
    if (i < N) {
        g_den[i] = 0.f;
        g_maxbits[i] = 0x007FFFFFu;  // fkey(-inf)
    }
}

// ---------------- fold1: extract strided weight views -------------------------
__global__ void fold1_kernel(const float* __restrict__ Wkv,
                             const float* __restrict__ bkv) {
    int idx = blockIdx.x * blockDim.x + threadIdx.x;
    if (idx < H * H) {
        int t = idx >> 7, m = idx & 127;
        g_wkh[idx] = Wkv[(9 + t) * KVDIM + 2 * m];
        g_wvh[idx] = Wkv[(9 + t) * KVDIM + 2 * m + 1];
    }
    if (idx < 9 * H) {
        int i = idx >> 7, m = idx & 127;
        g_wkr[idx] = Wkv[i * KVDIM + 2 * m];
        g_wvr[idx] = Wkv[i * KVDIM + 2 * m + 1];
    }
    if (idx < H) {
        g_bk[idx] = bkv[2 * idx];
        g_bv[idx] = bkv[2 * idx + 1];
    }
}

// ---------------- fold2: [Wvh; Wvr; bv] @ Wc1 ---------------------------------
__global__ void fold2_kernel(const float* __restrict__ Wc1) {
    int idx = blockIdx.x * blockDim.x + threadIdx.x;  // 138 * 512
    if (idx >= 138 * ZDIM) return;
    int t = idx / ZDIM, j = idx % ZDIM;
    const float* arow = (t < 128) ? &g_wvh[t * H]
                                  : ((t < 137) ? &g_wvr[(t - 128) * H] : g_bv);
    float acc = 0.f;
#pragma unroll 8
    for (int m = 0; m < H; m++) acc += arow[m] * Wc1[(size_t)m * ZDIM + j];
    if (t < 128) g_whz[t * ZDIM + j] = acc;
    else if (t < 137) g_wvc1[(t - 128) * ZDIM + j] = acc;
    else g_bz[j] = acc;
}

// ---------------- node GEMM  C(N x M) = A(N x 128) @ B + bias ----------------
__global__ __launch_bounds__(256, 2) void node_gemm(
    const float* __restrict__ A, const float* __restrict__ B, int ldb,
    const float* __restrict__ bias, float* __restrict__ C, int ldc, int N) {
    extern __shared__ float smem[];
    float* As = smem;               // [128][GPAD]
    float* Ws = smem + 128 * GPAD;  // [32][GPAD]
    int tid = threadIdx.x;
    int tx = tid & 15, ty = tid >> 4;
    int n0 = blockIdx.x * 128;
    int nt = blockIdx.y * 128;

#pragma unroll
    for (int it = 0; it < 16; it++) {
        int t4 = tid + 256 * it;
        int er = t4 >> 5, cf = t4 & 31;
        int r = n0 + er;
        float4 f = (r < N) ? *((const float4*)A + (size_t)r * 32 + cf)
                           : make_float4(0.f, 0.f, 0.f, 0.f);
        *(float4*)&As[er * GPAD + cf * 4] = f;
    }

    unsigned long long acc[8][4];
#pragma unroll
    for (int i = 0; i < 8; i++)
#pragma unroll
        for (int j = 0; j < 4; j++) acc[i][j] = 0ull;

    for (int k0 = 0; k0 < 128; k0 += 32) {
        __syncthreads();
#pragma unroll
        for (int it = 0; it < 4; it++) {
            int t4 = tid + 256 * it;
            int kk = t4 >> 5, cf = t4 & 31;
            float4 f = *(const float4*)&B[(size_t)(k0 + kk) * ldb + nt + cf * 4];
            *(float4*)&Ws[kk * GPAD + cf * 4] = f;
        }
        __syncthreads();
#pragma unroll 4
        for (int kk = 0; kk < 32; kk++) {
            ulonglong2 wa = *(const ulonglong2*)&Ws[kk * GPAD + tx * 8];
            ulonglong2 wb = *(const ulonglong2*)&Ws[kk * GPAD + tx * 8 + 4];
#pragma unroll
            for (int i = 0; i < 8; i++) {
                float v = As[(ty * 8 + i) * GPAD + k0 + kk];
                unsigned long long v2 = pack2(v, v);
                fma2(acc[i][0], v2, wa.x);
                fma2(acc[i][1], v2, wa.y);
                fma2(acc[i][2], v2, wb.x);
                fma2(acc[i][3], v2, wb.y);
            }
        }
    }
#pragma unroll
    for (int i = 0; i < 8; i++) {
        int r = n0 + ty * 8 + i;
        if (r >= N) continue;
#pragma unroll
        for (int j = 0; j < 4; j++) {
            int n = nt + tx * 8 + 2 * j;
            float lov = lo32(acc[i][j]) + bias[n];
            float hiv = hi32(acc[i][j]) + bias[n + 1];
            *(float2*)&C[(size_t)r * ldc + n] = make_float2(lov, hiv);
        }
    }
}

// ---------------- P kernel: P[r][i] = hq[r] . wkr[i] --------------------------
__global__ void p_kernel(int N) {
    int idx = blockIdx.x * blockDim.x + threadIdx.x;
    if (idx >= N * 9) return;
    int r = idx / 9, i = idx % 9;
    const float* a = &g_hq[(size_t)r * H];
    const float* b = &g_wkr[i * H];
    float acc = 0.f;
#pragma unroll 8
    for (int m = 0; m < H; m++) acc += a[m] * b[m];
    g_P[idx] = acc;
}

// ---------------- edge alpha: warp per edge -----------------------------------
__global__ void edge_alpha_kernel(const float* __restrict__ coord,
                                  const int* __restrict__ row,
                                  const int* __restrict__ col, int E) {
    int gw = (int)((blockIdx.x * blockDim.x + threadIdx.x) >> 5);
    int lane = threadIdx.x & 31;
    if (gw >= E) return;
    int r = row[gw], c = col[gw];

    float cdv = 0.f;
    if (lane < 9) cdv = coord[(size_t)r * 9 + lane] - coord[(size_t)c * 9 + lane];
    float cd[9];
#pragma unroll
    for (int i = 0; i < 9; i++) cd[i] = __shfl_sync(0xffffffffu, cdv, i);
    if (lane < 9) g_cd[(size_t)gw * 9 + lane] = cdv;

    float ap = 0.f;
#pragma unroll
    for (int t = 0; t < 4; t++) {
        int m = lane + 32 * t;
        ap += g_hq[(size_t)r * H + m] * g_hk[(size_t)c * H + m];
    }
    if (lane < 9) {
        int a = lane / 3, b = lane % 3;
        float rad = cd[a * 3] * cd[b * 3] + cd[a * 3 + 1] * cd[b * 3 + 1] +
                    cd[a * 3 + 2] * cd[b * 3 + 2];
        ap += rad * g_P[r * 9 + lane];
    }
#pragma unroll
    for (int o = 16; o; o >>= 1) ap += __shfl_xor_sync(0xffffffffu, ap, o);
    if (lane == 0) {
        g_araw[gw] = ap;
        atomicMax(&g_maxbits[r], fkey(ap));
    }
}

// ---------------- softmax denominator -----------------------------------------
__global__ void softmax_den_kernel(const int* __restrict__ row, int E) {
    int e = blockIdx.x * blockDim.x + threadIdx.x;
    if (e >= E) return;
    int r = row[e];
    float amax = fdec(g_maxbits[r]);
    float ex = expf(g_araw[e] - amax);
    g_ex[e] = ex;
    atomicAdd(&g_den[r], ex);
}

// ---------------- heavy: per-128-edge tile ------------------------------------
// cv = silu(Z[col] + rad@Wvc1) @ Wc2 ; coord scatter ; agg += alpha*v
__global__ __launch_bounds__(256) void heavy_kernel(
    const float* __restrict__ Wc2, const int* __restrict__ row,
    const int* __restrict__ col, float* __restrict__ alpha_out, int E) {
    __shared__ float cd_s[128 * 9];
    __shared__ float rad_s[128 * 9];
    __shared__ float wvr_s[9 * H];
    __shared__ float cv_s[128 * 3];
    __shared__ float alpha_s[128];
    __shared__ int   row_s[128];
    __shared__ int   col_s[128];

    int tid = threadIdx.x;
    int e0 = blockIdx.x * 128;

    for (int i = tid; i < 1152; i += 256) {
        size_t g = (size_t)e0 * 9 + i;
        cd_s[i] = (g < (size_t)E * 9) ? g_cd[g] : 0.f;
        wvr_s[i] = g_wvr[i];
    }
    if (tid < 128) {
        int e = e0 + tid;
        if (e < E) {
            int r = row[e];
            row_s[tid] = r;
            col_s[tid] = col[e];
            alpha_s[tid] = g_ex[e] / g_den[r];
        } else {
            row_s[tid] = -1;
            col_s[tid] = 0;
            alpha_s[tid] = 0.f;
        }
    }
    for (int i = tid; i < 384; i += 256) cv_s[i] = 0.f;
    __syncthreads();
    if (tid < 128) {
        const float* cd = &cd_s[tid * 9];
#pragma unroll
        for (int a = 0; a < 3; a++)
#pragma unroll
            for (int b = 0; b < 3; b++)
                rad_s[tid * 9 + a * 3 + b] = cd[a * 3] * cd[b * 3] +
                                             cd[a * 3 + 1] * cd[b * 3 + 1] +
                                             cd[a * 3 + 2] * cd[b * 3 + 2];
    }
    __syncthreads();

    // ---- cv phase: 2 edge-lanes x 128 col-threads (4 cols each) ----
    {
        int ct = tid & 127;
        int el = tid >> 7;
        int j0 = ct * 4;
        float wv[9][4];
#pragma unroll
        for (int i = 0; i < 9; i++) {
            float4 f = *(const float4*)&g_wvc1[i * ZDIM + j0];
            wv[i][0] = f.x; wv[i][1] = f.y; wv[i][2] = f.z; wv[i][3] = f.w;
        }
        float w2[4][3];
#pragma unroll
        for (int jj = 0; jj < 4; jj++)
#pragma unroll
            for (int d = 0; d < 3; d++) w2[jj][d] = Wc2[(j0 + jj) * 3 + d];

        int lane = tid & 31;
        for (int eg = 0; eg < 64; eg++) {
            int er = eg * 2 + el;
            int c = col_s[er];
            float4 z = *(const float4*)&g_Z[(size_t)c * ZDIM + j0];
            float x[4] = {z.x, z.y, z.z, z.w};
#pragma unroll
            for (int i = 0; i < 9; i++) {
                float ri = rad_s[er * 9 + i];
#pragma unroll
                for (int jj = 0; jj < 4; jj++) x[jj] += ri * wv[i][jj];
            }
            float p0 = 0.f, p1 = 0.f, p2 = 0.f;
#pragma unroll
            for (int jj = 0; jj < 4; jj++) {
                float u = x[jj] / (1.f + __expf(-x[jj]));
                p0 += u * w2[jj][0];
                p1 += u * w2[jj][1];
                p2 += u * w2[jj][2];
            }
#pragma unroll
            for (int o = 16; o; o >>= 1) {
                p0 += __shfl_xor_sync(0xffffffffu, p0, o);
                p1 += __shfl_xor_sync(0xffffffffu, p1, o);
                p2 += __shfl_xor_sync(0xffffffffu, p2, o);
            }
            if (lane == 0) {
                atomicAdd(&cv_s[er * 3 + 0], p0);
                atomicAdd(&cv_s[er * 3 + 1], p1);
                atomicAdd(&cv_s[er * 3 + 2], p2);
            }
        }
    }

    // ---- agg phase: v = hv[col] + rad@wvr ; agg += alpha*v ----
    {
        int m = tid & 127;
        int el = tid >> 7;
        float wv2[9];
#pragma unroll
        for (int i = 0; i < 9; i++) wv2[i] = wvr_s[i * H + m];
        for (int eg = 0; eg < 64; eg++) {
            int er = eg * 2 + el;
            int rrow = row_s[er];
            if (rrow < 0) continue;
            int c = col_s[er];
            float v = g_hv[(size_t)c * H + m];
#pragma unroll
            for (int i = 0; i < 9; i++) v += rad_s[er * 9 + i] * wv2[i];
            atomicAdd(&g_agg[(size_t)rrow * H + m], alpha_s[er] * v);
        }
    }
    __syncthreads();

    // ---- coord scatter + alpha output ----
    if (tid < 128) {
        int e = e0 + tid;
        if (e < E) {
            float a = alpha_s[tid];
            alpha_out[e] = a;
            int r = row_s[tid];
            float c0 = cv_s[tid * 3 + 0] * a;
            float c1 = cv_s[tid * 3 + 1] * a;
            float c2 = cv_s[tid * 3 + 2] * a;
#pragma unroll
            for (int d = 0; d < 3; d++) {
                atomicAdd(&g_cagg[r * 9 + d],     cd_s[tid * 9 + d] * c0);
                atomicAdd(&g_cagg[r * 9 + 3 + d], cd_s[tid * 9 + 3 + d] * c1);
                atomicAdd(&g_cagg[r * 9 + 6 + d], cd_s[tid * 9 + 6 + d] * c2);
            }
        }
    }
}

// ---------------- finalize ----------------------------------------------------
__global__ void finalize_kernel(const float* __restrict__ h,
                                const float* __restrict__ coord,
                                float* __restrict__ out, int N) {
    int i = blockIdx.x * blockDim.x + threadIdx.x;
    int nh = N * H;
    if (i < nh) {
        out[i] = h[i] + g_agg[i];
    } else {
        int j = i - nh;
        if (j < N * 9) {
            float cg = g_cagg[j];
            cg = fminf(fmaxf(cg, -10.f), 10.f);
            out[nh + j] = coord[j] + cg;
        }
    }
}

// ---------------- launch ------------------------------------------------------
extern "C" void kernel_launch(void* const* d_in, const int* in_sizes, int n_in,
                              void* d_out, int out_size) {
    const float* h = (const float*)d_in[0];
    const float* coord = (const float*)d_in[1];
    const int* row = (const int*)d_in[2];
    const int* col = (const int*)d_in[3];
    const float* Wq = (const float*)d_in[4];
    const float* bq = (const float*)d_in[5];
    const float* Wkv = (const float*)d_in[6];
    const float* bkv = (const float*)d_in[7];
    const float* Wc1 = (const float*)d_in[8];
    const float* Wc2 = (const float*)d_in[9];
    int N = in_sizes[0] / H;
    int E = in_sizes[2];
    float* out = (float*)d_out;

    size_t smem_g = (size_t)(128 * GPAD + 32 * GPAD) * sizeof(float);
    cudaFuncSetAttribute((const void*)node_gemm,
                         cudaFuncAttributeMaxDynamicSharedMemorySize, (int)smem_g);

    float *hq_p, *hk_p, *hv_p, *z_p;
    float *wkh_p, *wvh_p, *whz_p, *bk_p, *bv_p, *bz_p;
    cudaGetSymbolAddress((void**)&hq_p, g_hq);
    cudaGetSymbolAddress((void**)&hk_p, g_hk);
    cudaGetSymbolAddress((void**)&hv_p, g_hv);
    cudaGetSymbolAddress((void**)&z_p, g_Z);
    cudaGetSymbolAddress((void**)&wkh_p, g_wkh);
    cudaGetSymbolAddress((void**)&wvh_p, g_wvh);
    cudaGetSymbolAddress((void**)&whz_p, g_whz);
    cudaGetSymbolAddress((void**)&bk_p, g_bk);
    cudaGetSymbolAddress((void**)&bv_p, g_bv);
    cudaGetSymbolAddress((void**)&bz_p, g_bz);

    init_kernel<<<(N * H + 255) / 256, 256>>>(N);
    fold1_kernel<<<(H * H + 255) / 256, 256>>>(Wkv, bkv);
    fold2_kernel<<<(138 * ZDIM + 255) / 256, 256>>>(Wc1);

    dim3 g1((N + 127) / 128, 1);
    node_gemm<<<g1, 256, smem_g>>>(h, Wq, H, bq, hq_p, H, N);
    node_gemm<<<g1, 256, smem_g>>>(h, wkh_p, H, bk_p, hk_p, H, N);
    node_gemm<<<g1, 256, smem_g>>>(h, wvh_p, H, bv_p, hv_p, H, N);
    dim3 g4((N + 127) / 128, 4);
    node_gemm<<<g4, 256, smem_g>>>(h, whz_p, ZDIM, bz_p, z_p, ZDIM, N);

    p_kernel<<<(N * 9 + 255) / 256, 256>>>(N);
    edge_alpha_kernel<<<(E + 7) / 8, 256>>>(coord, row, col, E);
    softmax_den_kernel<<<(E + 255) / 256, 256>>>(row, E);

    heavy_kernel<<<(E + 127) / 128, 256>>>(
        Wc2, row, col, out + (size_t)N * H + (size_t)N * 9, E);

    finalize_kernel<<<(N * H + N * 9 + 255) / 256, 256>>>(h, coord, out, N);
}

// round 3
// speedup vs baseline: 5.5668x; 1.5935x over previous
#include <cuda_runtime.h>
#include <math.h>

#define H 128
#define KVDIM 256
#define ZDIM 512
#define NMAX 50000
#define EMAX 500000
#define GPAD 132

// ---------------- scratch ------------------------------------------------------
__device__ float    g_hq[NMAX * H];
__device__ float    g_hk[NMAX * H];
__device__ float    g_hv[NMAX * H];
__device__ float    g_Z[NMAX * ZDIM];
__device__ float    g_P[NMAX * 9];
// CSR
__device__ int      g_cnt[NMAX];
__device__ int      g_off[NMAX + 1];
__device__ int      g_cur[NMAX];
__device__ int      g_perm[EMAX];
__device__ int      g_rows[EMAX];
__device__ int      g_cols[EMAX];
// sorted per-edge data
__device__ float    g_cds[EMAX * 9];
__device__ float    g_rads[EMAX * 9];
__device__ float    g_araw[EMAX];
__device__ float    g_cvs[EMAX * 3];
// folded weights
__device__ float    g_wkh[H * H];
__device__ float    g_wvh[H * H];
__device__ float    g_wkr[9 * H];
__device__ float    g_wvr[9 * H];
__device__ float    g_bk[H];
__device__ float    g_bv[H];
__device__ float    g_whz[H * ZDIM];
__device__ float    g_wvc1[9 * ZDIM];
__device__ float    g_bz[ZDIM];

// ---------------- helpers ------------------------------------------------------
__device__ __forceinline__ unsigned long long pack2(float x, float y) {
    unsigned long long r;
    asm("mov.b64 %0, {%1, %2};" : "=l"(r) : "f"(x), "f"(y));
    return r;
}
__device__ __forceinline__ void fma2(unsigned long long& d, unsigned long long a,
                                     unsigned long long b) {
    asm("fma.rn.f32x2 %0, %1, %2, %0;" : "+l"(d) : "l"(a), "l"(b));
}
__device__ __forceinline__ float lo32(unsigned long long v) {
    return __uint_as_float((unsigned)v);
}
__device__ __forceinline__ float hi32(unsigned long long v) {
    return __uint_as_float((unsigned)(v >> 32));
}
__device__ __forceinline__ float silu_f(float x) {
    float t;
    asm("tanh.approx.f32 %0, %1;" : "=f"(t) : "f"(0.5f * x));
    return 0.5f * x * (1.f + t);
}

// ---------------- CSR build ----------------------------------------------------
__global__ void zero_kernel(int N) {
    int i = blockIdx.x * blockDim.x + threadIdx.x;
    if (i < N) g_cnt[i] = 0;
}
__global__ void hist_kernel(const int* __restrict__ row, int E) {
    int e = blockIdx.x * blockDim.x + threadIdx.x;
    if (e < E) atomicAdd(&g_cnt[row[e]], 1);
}
__global__ void scan_kernel(int N) {
    __shared__ int part[1024];
    int tid = threadIdx.x;
    int chunk = (N + 1023) / 1024;
    int s = tid * chunk;
    int e = min(s + chunk, N);
    int sum = 0;
    for (int i = s; i < e; i++) sum += g_cnt[i];
    part[tid] = sum;
    __syncthreads();
    for (int off = 1; off < 1024; off *= 2) {
        int v = (tid >= off) ? part[tid - off] : 0;
        __syncthreads();
        part[tid] += v;
        __syncthreads();
    }
    int run = tid ? part[tid - 1] : 0;
    for (int i = s; i < e; i++) {
        g_off[i] = run;
        g_cur[i] = run;
        run += g_cnt[i];
    }
    if (tid == 1023) g_off[N] = part[1023];
}
__global__ void scatter_kernel(const int* __restrict__ row,
                               const int* __restrict__ col, int E) {
    int e = blockIdx.x * blockDim.x + threadIdx.x;
    if (e >= E) return;
    int r = row[e];
    int pos = atomicAdd(&g_cur[r], 1);
    g_perm[pos] = e;
    g_rows[pos] = r;
    g_cols[pos] = col[e];
}

// ---------------- weight folds -------------------------------------------------
__global__ void fold1_kernel(const float* __restrict__ Wkv,
                             const float* __restrict__ bkv) {
    int idx = blockIdx.x * blockDim.x + threadIdx.x;
    if (idx < H * H) {
        int t = idx >> 7, m = idx & 127;
        g_wkh[idx] = Wkv[(9 + t) * KVDIM + 2 * m];
        g_wvh[idx] = Wkv[(9 + t) * KVDIM + 2 * m + 1];
    }
    if (idx < 9 * H) {
        int i = idx >> 7, m = idx & 127;
        g_wkr[idx] = Wkv[i * KVDIM + 2 * m];
        g_wvr[idx] = Wkv[i * KVDIM + 2 * m + 1];
    }
    if (idx < H) {
        g_bk[idx] = bkv[2 * idx];
        g_bv[idx] = bkv[2 * idx + 1];
    }
}
__global__ void fold2_kernel(const float* __restrict__ Wc1) {
    int idx = blockIdx.x * blockDim.x + threadIdx.x;
    if (idx >= 138 * ZDIM) return;
    int t = idx / ZDIM, j = idx % ZDIM;
    const float* arow = (t < 128) ? &g_wvh[t * H]
                                  : ((t < 137) ? &g_wvr[(t - 128) * H] : g_bv);
    float acc = 0.f;
#pragma unroll 8
    for (int m = 0; m < H; m++) acc += arow[m] * Wc1[(size_t)m * ZDIM + j];
    if (t < 128) g_whz[t * ZDIM + j] = acc;
    else if (t < 137) g_wvc1[(t - 128) * ZDIM + j] = acc;
    else g_bz[j] = acc;
}

// ---------------- merged node GEMM (y selects output) -------------------------
__global__ __launch_bounds__(256, 2) void node_gemm_all(
    const float* __restrict__ A, const float* __restrict__ Wq,
    const float* __restrict__ bq, int N) {
    extern __shared__ float smem[];
    float* As = smem;               // [128][GPAD]
    float* Ws = smem + 128 * GPAD;  // [32][GPAD]
    int tid = threadIdx.x;
    int tx = tid & 15, ty = tid >> 4;
    int n0 = blockIdx.x * 128;
    int y = blockIdx.y;

    const float* B;
    const float* bias;
    float* C;
    int ldb, ldc, nt;
    if (y == 0)      { B = Wq;    bias = bq;   C = g_hq; ldb = H;    ldc = H;    nt = 0; }
    else if (y == 1) { B = g_wkh; bias = g_bk; C = g_hk; ldb = H;    ldc = H;    nt = 0; }
    else if (y == 2) { B = g_wvh; bias = g_bv; C = g_hv; ldb = H;    ldc = H;    nt = 0; }
    else             { B = g_whz; bias = g_bz; C = g_Z;  ldb = ZDIM; ldc = ZDIM; nt = (y - 3) * 128; }

#pragma unroll
    for (int it = 0; it < 16; it++) {
        int t4 = tid + 256 * it;
        int er = t4 >> 5, cf = t4 & 31;
        int r = n0 + er;
        float4 f = (r < N) ? *((const float4*)A + (size_t)r * 32 + cf)
                           : make_float4(0.f, 0.f, 0.f, 0.f);
        *(float4*)&As[er * GPAD + cf * 4] = f;
    }

    unsigned long long acc[8][4];
#pragma unroll
    for (int i = 0; i < 8; i++)
#pragma unroll
        for (int j = 0; j < 4; j++) acc[i][j] = 0ull;

    for (int k0 = 0; k0 < 128; k0 += 32) {
        __syncthreads();
#pragma unroll
        for (int it = 0; it < 4; it++) {
            int t4 = tid + 256 * it;
            int kk = t4 >> 5, cf = t4 & 31;
            float4 f = *(const float4*)&B[(size_t)(k0 + kk) * ldb + nt + cf * 4];
            *(float4*)&Ws[kk * GPAD + cf * 4] = f;
        }
        __syncthreads();
#pragma unroll 4
        for (int kk = 0; kk < 32; kk++) {
            ulonglong2 wa = *(const ulonglong2*)&Ws[kk * GPAD + tx * 8];
            ulonglong2 wb = *(const ulonglong2*)&Ws[kk * GPAD + tx * 8 + 4];
#pragma unroll
            for (int i = 0; i < 8; i++) {
                float v = As[(ty * 8 + i) * GPAD + k0 + kk];
                unsigned long long v2 = pack2(v, v);
                fma2(acc[i][0], v2, wa.x);
                fma2(acc[i][1], v2, wa.y);
                fma2(acc[i][2], v2, wb.x);
                fma2(acc[i][3], v2, wb.y);
            }
        }
    }
#pragma unroll
    for (int i = 0; i < 8; i++) {
        int r = n0 + ty * 8 + i;
        if (r >= N) continue;
#pragma unroll
        for (int j = 0; j < 4; j++) {
            int n = nt + tx * 8 + 2 * j;
            float lov = lo32(acc[i][j]) + bias[n];
            float hiv = hi32(acc[i][j]) + bias[n + 1];
            *(float2*)&C[(size_t)r * ldc + n] = make_float2(lov, hiv);
        }
    }
}

// ---------------- P: warp per node --------------------------------------------
__global__ void p_kernel(int N) {
    int r = (int)((blockIdx.x * blockDim.x + threadIdx.x) >> 5);
    int lane = threadIdx.x & 31;
    if (r >= N) return;
    float4 q = *(const float4*)&g_hq[(size_t)r * H + lane * 4];
#pragma unroll
    for (int i = 0; i < 9; i++) {
        float4 w = *(const float4*)&g_wkr[i * H + lane * 4];
        float s = q.x * w.x + q.y * w.y + q.z * w.z + q.w * w.w;
#pragma unroll
        for (int o = 16; o; o >>= 1) s += __shfl_xor_sync(0xffffffffu, s, o);
        if (lane == 0) g_P[r * 9 + i] = s;
    }
}

// ---------------- edge prep (sorted order, warp per edge) ---------------------
__global__ void edge_prep_kernel(const float* __restrict__ coord, int E) {
    int p = (int)((blockIdx.x * blockDim.x + threadIdx.x) >> 5);
    int lane = threadIdx.x & 31;
    if (p >= E) return;
    int r = g_rows[p], c = g_cols[p];

    float cdv = 0.f;
    if (lane < 9) cdv = coord[(size_t)r * 9 + lane] - coord[(size_t)c * 9 + lane];
    if (lane < 9) g_cds[(size_t)p * 9 + lane] = cdv;
    float cd[9];
#pragma unroll
    for (int i = 0; i < 9; i++) cd[i] = __shfl_sync(0xffffffffu, cdv, i);

    float radv = 0.f;
    if (lane < 9) {
        int a = lane / 3, b = lane % 3;
        radv = cd[a * 3] * cd[b * 3] + cd[a * 3 + 1] * cd[b * 3 + 1] +
               cd[a * 3 + 2] * cd[b * 3 + 2];
        g_rads[(size_t)p * 9 + lane] = radv;
    }

    float4 q = *(const float4*)&g_hq[(size_t)r * H + lane * 4];
    float4 k = *(const float4*)&g_hk[(size_t)c * H + lane * 4];
    float ap = q.x * k.x + q.y * k.y + q.z * k.z + q.w * k.w;
    if (lane < 9) ap += radv * g_P[r * 9 + lane];
#pragma unroll
    for (int o = 16; o; o >>= 1) ap += __shfl_xor_sync(0xffffffffu, ap, o);
    if (lane == 0) g_araw[p] = ap;
}

// ---------------- cv kernel: warp per 8 edges ---------------------------------
__global__ __launch_bounds__(256) void cv_kernel(const float* __restrict__ Wc2,
                                                 int E) {
    int lane = threadIdx.x & 31;
    int wg = (int)((blockIdx.x * blockDim.x + threadIdx.x) >> 5);
    int e0 = wg * 8;
    if (e0 >= E) return;

    int cols[8];
    float rr[8];
#pragma unroll
    for (int g = 0; g < 8; g++) {
        int e = e0 + g;
        cols[g] = (e < E) ? g_cols[e] : 0;
        rr[g] = (lane < 9 && e < E) ? g_rads[(size_t)e * 9 + lane] : 0.f;
    }
    float pacc[8][3];
#pragma unroll
    for (int g = 0; g < 8; g++) pacc[g][0] = pacc[g][1] = pacc[g][2] = 0.f;

    for (int jc = 0; jc < 4; jc++) {
        int j0 = jc * 128 + lane * 4;
        float wv[9][4];
#pragma unroll
        for (int i = 0; i < 9; i++) {
            float4 f = *(const float4*)&g_wvc1[i * ZDIM + j0];
            wv[i][0] = f.x; wv[i][1] = f.y; wv[i][2] = f.z; wv[i][3] = f.w;
        }
        float w2[4][3];
#pragma unroll
        for (int jj = 0; jj < 4; jj++)
#pragma unroll
            for (int d = 0; d < 3; d++) w2[jj][d] = Wc2[(j0 + jj) * 3 + d];

#pragma unroll
        for (int g = 0; g < 8; g++) {
            float4 z = *(const float4*)&g_Z[(size_t)cols[g] * ZDIM + j0];
            float x0 = z.x, x1 = z.y, x2 = z.z, x3 = z.w;
#pragma unroll
            for (int i = 0; i < 9; i++) {
                float ri = __shfl_sync(0xffffffffu, rr[g], i);
                x0 += ri * wv[i][0];
                x1 += ri * wv[i][1];
                x2 += ri * wv[i][2];
                x3 += ri * wv[i][3];
            }
            float u0 = silu_f(x0), u1 = silu_f(x1), u2 = silu_f(x2), u3 = silu_f(x3);
#pragma unroll
            for (int d = 0; d < 3; d++)
                pacc[g][d] += u0 * w2[0][d] + u1 * w2[1][d] + u2 * w2[2][d] +
                              u3 * w2[3][d];
        }
    }
#pragma unroll
    for (int g = 0; g < 8; g++) {
        float p0 = pacc[g][0], p1 = pacc[g][1], p2 = pacc[g][2];
#pragma unroll
        for (int o = 16; o; o >>= 1) {
            p0 += __shfl_xor_sync(0xffffffffu, p0, o);
            p1 += __shfl_xor_sync(0xffffffffu, p1, o);
            p2 += __shfl_xor_sync(0xffffffffu, p2, o);
        }
        if (lane == 0 && e0 + g < E) {
            g_cvs[(size_t)(e0 + g) * 3 + 0] = p0;
            g_cvs[(size_t)(e0 + g) * 3 + 1] = p1;
            g_cvs[(size_t)(e0 + g) * 3 + 2] = p2;
        }
    }
}

// ---------------- row kernel: softmax + agg + finalize ------------------------
__global__ __launch_bounds__(256) void row_kernel(
    const float* __restrict__ h, const float* __restrict__ coord,
    float* __restrict__ out, float* __restrict__ alpha_out, int N) {
    __shared__ float wvr_s[9 * H];
    int tid = threadIdx.x, lane = tid & 31, w = tid >> 5;
    for (int i = tid; i < 9 * H; i += 256) wvr_s[i] = g_wvr[i];
    __syncthreads();
    int r = blockIdx.x * 8 + w;
    if (r >= N) return;
    int s = g_off[r], e = g_off[r + 1];

    float4 acc = make_float4(0.f, 0.f, 0.f, 0.f);
    float aS = 0.f, cg = 0.f;
    if (e > s) {
        float m = -1e30f;
        for (int p = s + lane; p < e; p += 32) m = fmaxf(m, g_araw[p]);
#pragma unroll
        for (int o = 16; o; o >>= 1)
            m = fmaxf(m, __shfl_xor_sync(0xffffffffu, m, o));
        float den = 0.f;
        for (int p = s + lane; p < e; p += 32) den += __expf(g_araw[p] - m);
#pragma unroll
        for (int o = 16; o; o >>= 1) den += __shfl_xor_sync(0xffffffffu, den, o);
        float invd = 1.f / den;

        int c3 = lane / 3;
        for (int p = s; p < e; p++) {
            float a = __expf(g_araw[p] - m) * invd;
            int c = g_cols[p];
            float4 hv = *(const float4*)&g_hv[(size_t)c * H + lane * 4];
            acc.x += a * hv.x;
            acc.y += a * hv.y;
            acc.z += a * hv.z;
            acc.w += a * hv.w;
            if (lane < 9) {
                aS += a * g_rads[(size_t)p * 9 + lane];
                cg += g_cds[(size_t)p * 9 + lane] * (a * g_cvs[(size_t)p * 3 + c3]);
            }
            if (lane == 0) alpha_out[g_perm[p]] = a;
        }
#pragma unroll
        for (int i = 0; i < 9; i++) {
            float asi = __shfl_sync(0xffffffffu, aS, i);
            acc.x += asi * wvr_s[i * H + lane * 4 + 0];
            acc.y += asi * wvr_s[i * H + lane * 4 + 1];
            acc.z += asi * wvr_s[i * H + lane * 4 + 2];
            acc.w += asi * wvr_s[i * H + lane * 4 + 3];
        }
    }
    float4 hh = *(const float4*)&h[(size_t)r * H + lane * 4];
    float4 o4 = make_float4(hh.x + acc.x, hh.y + acc.y, hh.z + acc.z, hh.w + acc.w);
    *(float4*)&out[(size_t)r * H + lane * 4] = o4;
    if (lane < 9) {
        float cgc = fminf(fmaxf(cg, -10.f), 10.f);
        out[(size_t)N * H + (size_t)r * 9 + lane] = coord[(size_t)r * 9 + lane] + cgc;
    }
}

// ---------------- launch -------------------------------------------------------
extern "C" void kernel_launch(void* const* d_in, const int* in_sizes, int n_in,
                              void* d_out, int out_size) {
    const float* h = (const float*)d_in[0];
    const float* coord = (const float*)d_in[1];
    const int* row = (const int*)d_in[2];
    const int* col = (const int*)d_in[3];
    const float* Wq = (const float*)d_in[4];
    const float* bq = (const float*)d_in[5];
    const float* Wkv = (const float*)d_in[6];
    const float* bkv = (const float*)d_in[7];
    const float* Wc1 = (const float*)d_in[8];
    const float* Wc2 = (const float*)d_in[9];
    int N = in_sizes[0] / H;
    int E = in_sizes[2];
    float* out = (float*)d_out;
    float* alpha_out = out + (size_t)N * H + (size_t)N * 9;

    size_t smem_g = (size_t)(128 * GPAD + 32 * GPAD) * sizeof(float);
    cudaFuncSetAttribute((const void*)node_gemm_all,
                         cudaFuncAttributeMaxDynamicSharedMemorySize, (int)smem_g);

    // CSR build
    zero_kernel<<<(N + 255) / 256, 256>>>(N);
    hist_kernel<<<(E + 255) / 256, 256>>>(row, E);
    scan_kernel<<<1, 1024>>>(N);
    scatter_kernel<<<(E + 255) / 256, 256>>>(row, col, E);

    // weight folds + node GEMMs
    fold1_kernel<<<(H * H + 255) / 256, 256>>>(Wkv, bkv);
    fold2_kernel<<<(138 * ZDIM + 255) / 256, 256>>>(Wc1);
    dim3 gall((N + 127) / 128, 7);
    node_gemm_all<<<gall, 256, smem_g>>>(h, Wq, bq, N);

    p_kernel<<<(N * 32 + 255) / 256, 256>>>(N);
    edge_prep_kernel<<<(E * 32 + 255) / 256, 256>>>(coord, E);
    cv_kernel<<<((E + 7) / 8 * 32 + 255) / 256, 256>>>(Wc2, E);
    row_kernel<<<(N + 7) / 8, 256>>>(h, coord, out, alpha_out, N);
}

// round 6
// speedup vs baseline: 6.3351x; 1.1380x over previous
#include <cuda_runtime.h>
#include <cuda_bf16.h>
#include <stdint.h>
#include <math.h>

#define H 128
#define KVDIM 256
#define ZDIM 512
#define NMAX 50000
#define EMAX 500000
#define GPAD 132
#define BSTRIDE 136   // bf16 elements per padded smem row (272B, 68 words)

// ---------------- scratch ------------------------------------------------------
__device__ float    g_hq[NMAX * H];
__device__ float    g_hk[NMAX * H];
__device__ float    g_hv[NMAX * H];
__device__ unsigned g_Zb[NMAX * (ZDIM / 2)];   // Z as packed bf16x2
__device__ float    g_P[NMAX * 9];
// CSR
__device__ int      g_cnt[NMAX];
__device__ int      g_off[NMAX + 1];
__device__ int      g_cur[NMAX];
__device__ int      g_perm[EMAX];
__device__ int      g_rows[EMAX];
__device__ int      g_cols[EMAX];
// sorted per-edge data
__device__ float    g_cds[EMAX * 9];
__device__ float    g_rads[EMAX * 9];
__device__ float    g_araw[EMAX];
__device__ float    g_cvs[EMAX * 3];
// folded weights
__device__ float    g_wkh[H * H];
__device__ float    g_wvh[H * H];
__device__ float    g_wkr[9 * H];
__device__ float    g_wvr[9 * H];
__device__ float    g_bk[H];
__device__ float    g_bv[H];
__device__ float    g_whz[H * ZDIM];
__device__ float    g_wvc1[9 * ZDIM];
__device__ float    g_bz[ZDIM];

// ---------------- helpers ------------------------------------------------------
__device__ __forceinline__ unsigned long long pack2(float x, float y) {
    unsigned long long r;
    asm("mov.b64 %0, {%1, %2};" : "=l"(r) : "f"(x), "f"(y));
    return r;
}
__device__ __forceinline__ void fma2(unsigned long long& d, unsigned long long a,
                                     unsigned long long b) {
    asm("fma.rn.f32x2 %0, %1, %2, %0;" : "+l"(d) : "l"(a), "l"(b));
}
__device__ __forceinline__ float lo32(unsigned long long v) {
    return __uint_as_float((unsigned)v);
}
__device__ __forceinline__ float hi32(unsigned long long v) {
    return __uint_as_float((unsigned)(v >> 32));
}
__device__ __forceinline__ float silu_f(float x) {
    float t;
    asm("tanh.approx.f32 %0, %1;" : "=f"(t) : "f"(0.5f * x));
    return 0.5f * x * (1.f + t);
}
__device__ __forceinline__ unsigned bf16x2_of(float x0, float x1) {
    unsigned r;
    asm("cvt.rn.bf16x2.f32 %0, %1, %2;" : "=r"(r) : "f"(x1), "f"(x0));
    return r;
}
__device__ __forceinline__ unsigned short bf16_of(float x) {
    unsigned u = __float_as_uint(x);
    u += 0x7fffu + ((u >> 16) & 1u);
    return (unsigned short)(u >> 16);
}
__device__ __forceinline__ void mma_bf16(float c[4], uint32_t a0, uint32_t a1,
                                         uint32_t a2, uint32_t a3, uint32_t b0,
                                         uint32_t b1) {
    asm volatile(
        "mma.sync.aligned.m16n8k16.row.col.f32.bf16.bf16.f32 "
        "{%0,%1,%2,%3}, {%4,%5,%6,%7}, {%8,%9}, {%0,%1,%2,%3};"
        : "+f"(c[0]), "+f"(c[1]), "+f"(c[2]), "+f"(c[3])
        : "r"(a0), "r"(a1), "r"(a2), "r"(a3), "r"(b0), "r"(b1));
}

// ---------------- CSR build ----------------------------------------------------
__global__ void zero_kernel(int N) {
    int i = blockIdx.x * blockDim.x + threadIdx.x;
    if (i < N) g_cnt[i] = 0;
}
__global__ void hist_kernel(const int* __restrict__ row, int E) {
    int e = blockIdx.x * blockDim.x + threadIdx.x;
    if (e < E) atomicAdd(&g_cnt[row[e]], 1);
}
__global__ void scan_kernel(int N) {
    __shared__ int part[1024];
    int tid = threadIdx.x;
    int chunk = (N + 1023) / 1024;
    int s = tid * chunk;
    int e = min(s + chunk, N);
    int sum = 0;
    for (int i = s; i < e; i++) sum += g_cnt[i];
    part[tid] = sum;
    __syncthreads();
    for (int off = 1; off < 1024; off *= 2) {
        int v = (tid >= off) ? part[tid - off] : 0;
        __syncthreads();
        part[tid] += v;
        __syncthreads();
    }
    int run = tid ? part[tid - 1] : 0;
    for (int i = s; i < e; i++) {
        g_off[i] = run;
        g_cur[i] = run;
        run += g_cnt[i];
    }
    if (tid == 1023) g_off[N] = part[1023];
}
__global__ void scatter_kernel(const int* __restrict__ row,
                               const int* __restrict__ col, int E) {
    int e = blockIdx.x * blockDim.x + threadIdx.x;
    if (e >= E) return;
    int r = row[e];
    int pos = atomicAdd(&g_cur[r], 1);
    g_perm[pos] = e;
    g_rows[pos] = r;
    g_cols[pos] = col[e];
}

// ---------------- weight folds -------------------------------------------------
__global__ void fold1_kernel(const float* __restrict__ Wkv,
                             const float* __restrict__ bkv) {
    int idx = blockIdx.x * blockDim.x + threadIdx.x;
    if (idx < H * H) {
        int t = idx >> 7, m = idx & 127;
        g_wkh[idx] = Wkv[(9 + t) * KVDIM + 2 * m];
        g_wvh[idx] = Wkv[(9 + t) * KVDIM + 2 * m + 1];
    }
    if (idx < 9 * H) {
        int i = idx >> 7, m = idx & 127;
        g_wkr[idx] = Wkv[i * KVDIM + 2 * m];
        g_wvr[idx] = Wkv[i * KVDIM + 2 * m + 1];
    }
    if (idx < H) {
        g_bk[idx] = bkv[2 * idx];
        g_bv[idx] = bkv[2 * idx + 1];
    }
}
__global__ void fold2_kernel(const float* __restrict__ Wc1) {
    int idx = blockIdx.x * blockDim.x + threadIdx.x;
    if (idx >= 138 * ZDIM) return;
    int t = idx / ZDIM, j = idx % ZDIM;
    const float* arow = (t < 128) ? &g_wvh[t * H]
                                  : ((t < 137) ? &g_wvr[(t - 128) * H] : g_bv);
    float acc = 0.f;
#pragma unroll 8
    for (int m = 0; m < H; m++) acc += arow[m] * Wc1[(size_t)m * ZDIM + j];
    if (t < 128) g_whz[t * ZDIM + j] = acc;
    else if (t < 137) g_wvc1[(t - 128) * ZDIM + j] = acc;
    else g_bz[j] = acc;
}

// ---------------- FFMA2 node GEMM (hq, hk, hv only) ---------------------------
__global__ __launch_bounds__(256, 2) void node_gemm_all(
    const float* __restrict__ A, const float* __restrict__ Wq,
    const float* __restrict__ bq, int N) {
    extern __shared__ float smem[];
    float* As = smem;               // [128][GPAD]
    float* Ws = smem + 128 * GPAD;  // [32][GPAD]
    int tid = threadIdx.x;
    int tx = tid & 15, ty = tid >> 4;
    int n0 = blockIdx.x * 128;
    int y = blockIdx.y;

    const float* B;
    const float* bias;
    float* C;
    if (y == 0)      { B = Wq;    bias = bq;   C = g_hq; }
    else if (y == 1) { B = g_wkh; bias = g_bk; C = g_hk; }
    else             { B = g_wvh; bias = g_bv; C = g_hv; }

#pragma unroll
    for (int it = 0; it < 16; it++) {
        int t4 = tid + 256 * it;
        int er = t4 >> 5, cf = t4 & 31;
        int r = n0 + er;
        float4 f = (r < N) ? *((const float4*)A + (size_t)r * 32 + cf)
                           : make_float4(0.f, 0.f, 0.f, 0.f);
        *(float4*)&As[er * GPAD + cf * 4] = f;
    }

    unsigned long long acc[8][4];
#pragma unroll
    for (int i = 0; i < 8; i++)
#pragma unroll
        for (int j = 0; j < 4; j++) acc[i][j] = 0ull;

    for (int k0 = 0; k0 < 128; k0 += 32) {
        __syncthreads();
#pragma unroll
        for (int it = 0; it < 4; it++) {
            int t4 = tid + 256 * it;
            int kk = t4 >> 5, cf = t4 & 31;
            float4 f = *(const float4*)&B[(size_t)(k0 + kk) * H + cf * 4];
            *(float4*)&Ws[kk * GPAD + cf * 4] = f;
        }
        __syncthreads();
#pragma unroll 4
        for (int kk = 0; kk < 32; kk++) {
            ulonglong2 wa = *(const ulonglong2*)&Ws[kk * GPAD + tx * 8];
            ulonglong2 wb = *(const ulonglong2*)&Ws[kk * GPAD + tx * 8 + 4];
#pragma unroll
            for (int i = 0; i < 8; i++) {
                float v = As[(ty * 8 + i) * GPAD + k0 + kk];
                unsigned long long v2 = pack2(v, v);
                fma2(acc[i][0], v2, wa.x);
                fma2(acc[i][1], v2, wa.y);
                fma2(acc[i][2], v2, wb.x);
                fma2(acc[i][3], v2, wb.y);
            }
        }
    }
#pragma unroll
    for (int i = 0; i < 8; i++) {
        int r = n0 + ty * 8 + i;
        if (r >= N) continue;
#pragma unroll
        for (int j = 0; j < 4; j++) {
            int n = tx * 8 + 2 * j;
            float lov = lo32(acc[i][j]) + bias[n];
            float hiv = hi32(acc[i][j]) + bias[n + 1];
            *(float2*)&C[(size_t)r * H + n] = make_float2(lov, hiv);
        }
    }
}

// ---------------- mma.sync bf16 Z GEMM: Zb = bf16(h @ whz + bz) ---------------
// block: 128 rows x 128 cols of Z; 8 warps each 32x64; K = 128.
__global__ __launch_bounds__(256) void zgemm_kernel(const float* __restrict__ h,
                                                    int N) {
    extern __shared__ unsigned short zsm[];
    unsigned short* As = zsm;                  // [128][BSTRIDE]
    unsigned short* Bs = zsm + 128 * BSTRIDE;  // [128][BSTRIDE] (n-major, k inner)

    int tid = threadIdx.x;
    int wid = tid >> 5, lane = tid & 31;
    int gid = lane >> 2, tig = lane & 3;
    int n0 = blockIdx.x * 128;
    int nt = blockIdx.y * 128;

    // A: h rows -> bf16, row-major [row][k]
    for (int idx = tid; idx < 128 * 64; idx += 256) {
        int row = idx >> 6, j = idx & 63;
        float2 f = make_float2(0.f, 0.f);
        if (n0 + row < N) f = *(const float2*)&h[(size_t)(n0 + row) * H + 2 * j];
        *(unsigned*)&As[row * BSTRIDE + 2 * j] = bf16x2_of(f.x, f.y);
    }
    // B: Bs[n][k] = whz[k][nt+n] (transpose in smem)
    for (int idx = tid; idx < 128 * 128; idx += 256) {
        int k = idx >> 7, n = idx & 127;
        Bs[n * BSTRIDE + k] = bf16_of(g_whz[(size_t)k * ZDIM + nt + n]);
    }
    __syncthreads();

    int wm = (wid & 3) * 32;
    int wn = (wid >> 2) * 64;

    float c[2][8][4];
#pragma unroll
    for (int mt = 0; mt < 2; mt++)
#pragma unroll
        for (int ntl = 0; ntl < 8; ntl++)
#pragma unroll
            for (int q = 0; q < 4; q++) c[mt][ntl][q] = 0.f;

#pragma unroll
    for (int k0 = 0; k0 < 128; k0 += 16) {
        uint32_t a[2][4];
#pragma unroll
        for (int mt = 0; mt < 2; mt++) {
            int row = wm + mt * 16;
            a[mt][0] = *(const unsigned*)&As[(row + gid) * BSTRIDE + k0 + 2 * tig];
            a[mt][1] = *(const unsigned*)&As[(row + gid + 8) * BSTRIDE + k0 + 2 * tig];
            a[mt][2] = *(const unsigned*)&As[(row + gid) * BSTRIDE + k0 + 2 * tig + 8];
            a[mt][3] = *(const unsigned*)&As[(row + gid + 8) * BSTRIDE + k0 + 2 * tig + 8];
        }
        uint32_t b[8][2];
#pragma unroll
        for (int ntl = 0; ntl < 8; ntl++) {
            int col = wn + ntl * 8 + gid;
            b[ntl][0] = *(const unsigned*)&Bs[col * BSTRIDE + k0 + 2 * tig];
            b[ntl][1] = *(const unsigned*)&Bs[col * BSTRIDE + k0 + 2 * tig + 8];
        }
#pragma unroll
        for (int mt = 0; mt < 2; mt++)
#pragma unroll
            for (int ntl = 0; ntl < 8; ntl++)
                mma_bf16(c[mt][ntl], a[mt][0], a[mt][1], a[mt][2], a[mt][3],
                         b[ntl][0], b[ntl][1]);
    }

    // epilogue: add bz, pack bf16x2, write Zb
#pragma unroll
    for (int mt = 0; mt < 2; mt++) {
        int r0 = n0 + wm + mt * 16 + gid;
#pragma unroll
        for (int ntl = 0; ntl < 8; ntl++) {
            int gcol = nt + wn + ntl * 8 + 2 * tig;
            float bz0 = g_bz[gcol], bz1 = g_bz[gcol + 1];
            if (r0 < N)
                g_Zb[(size_t)r0 * (ZDIM / 2) + (gcol >> 1)] =
                    bf16x2_of(c[mt][ntl][0] + bz0, c[mt][ntl][1] + bz1);
            if (r0 + 8 < N)
                g_Zb[(size_t)(r0 + 8) * (ZDIM / 2) + (gcol >> 1)] =
                    bf16x2_of(c[mt][ntl][2] + bz0, c[mt][ntl][3] + bz1);
        }
    }
}

// ---------------- P: warp per node --------------------------------------------
__global__ void p_kernel(int N) {
    int r = (int)((blockIdx.x * blockDim.x + threadIdx.x) >> 5);
    int lane = threadIdx.x & 31;
    if (r >= N) return;
    float4 q = *(const float4*)&g_hq[(size_t)r * H + lane * 4];
#pragma unroll
    for (int i = 0; i < 9; i++) {
        float4 w = *(const float4*)&g_wkr[i * H + lane * 4];
        float s = q.x * w.x + q.y * w.y + q.z * w.z + q.w * w.w;
#pragma unroll
        for (int o = 16; o; o >>= 1) s += __shfl_xor_sync(0xffffffffu, s, o);
        if (lane == 0) g_P[r * 9 + i] = s;
    }
}

// ---------------- edge prep (sorted order, warp per edge) ---------------------
__global__ void edge_prep_kernel(const float* __restrict__ coord, int E) {
    int p = (int)((blockIdx.x * blockDim.x + threadIdx.x) >> 5);
    int lane = threadIdx.x & 31;
    if (p >= E) return;
    int r = g_rows[p], c = g_cols[p];

    float cdv = 0.f;
    if (lane < 9) cdv = coord[(size_t)r * 9 + lane] - coord[(size_t)c * 9 + lane];
    if (lane < 9) g_cds[(size_t)p * 9 + lane] = cdv;
    float cd[9];
#pragma unroll
    for (int i = 0; i < 9; i++) cd[i] = __shfl_sync(0xffffffffu, cdv, i);

    float radv = 0.f;
    if (lane < 9) {
        int a = lane / 3, b = lane % 3;
        radv = cd[a * 3] * cd[b * 3] + cd[a * 3 + 1] * cd[b * 3 + 1] +
               cd[a * 3 + 2] * cd[b * 3 + 2];
        g_rads[(size_t)p * 9 + lane] = radv;
    }

    float4 q = *(const float4*)&g_hq[(size_t)r * H + lane * 4];
    float4 k = *(const float4*)&g_hk[(size_t)c * H + lane * 4];
    float ap = q.x * k.x + q.y * k.y + q.z * k.z + q.w * k.w;
    if (lane < 9) ap += radv * g_P[r * 9 + lane];
#pragma unroll
    for (int o = 16; o; o >>= 1) ap += __shfl_xor_sync(0xffffffffu, ap, o);
    if (lane == 0) g_araw[p] = ap;
}

// ---------------- cv kernel: warp per 8 edges (Z in bf16) ---------------------
__global__ __launch_bounds__(256) void cv_kernel(const float* __restrict__ Wc2,
                                                 int E) {
    int lane = threadIdx.x & 31;
    int wg = (int)((blockIdx.x * blockDim.x + threadIdx.x) >> 5);
    int e0 = wg * 8;
    if (e0 >= E) return;

    int cols[8];
    float rr[8];
#pragma unroll
    for (int g = 0; g < 8; g++) {
        int e = e0 + g;
        cols[g] = (e < E) ? g_cols[e] : 0;
        rr[g] = (lane < 9 && e < E) ? g_rads[(size_t)e * 9 + lane] : 0.f;
    }
    float pacc[8][3];
#pragma unroll
    for (int g = 0; g < 8; g++) pacc[g][0] = pacc[g][1] = pacc[g][2] = 0.f;

    for (int jc = 0; jc < 4; jc++) {
        int j0 = jc * 128 + lane * 4;
        float wv[9][4];
#pragma unroll
        for (int i = 0; i < 9; i++) {
            float4 f = *(const float4*)&g_wvc1[i * ZDIM + j0];
            wv[i][0] = f.x; wv[i][1] = f.y; wv[i][2] = f.z; wv[i][3] = f.w;
        }
        float w2[4][3];
#pragma unroll
        for (int jj = 0; jj < 4; jj++)
#pragma unroll
            for (int d = 0; d < 3; d++) w2[jj][d] = Wc2[(j0 + jj) * 3 + d];

#pragma unroll
        for (int g = 0; g < 8; g++) {
            uint2 z = *(const uint2*)&g_Zb[(size_t)cols[g] * (ZDIM / 2) + (j0 >> 1)];
            float x0 = __uint_as_float(z.x << 16);
            float x1 = __uint_as_float(z.x & 0xffff0000u);
            float x2 = __uint_as_float(z.y << 16);
            float x3 = __uint_as_float(z.y & 0xffff0000u);
#pragma unroll
            for (int i = 0; i < 9; i++) {
                float ri = __shfl_sync(0xffffffffu, rr[g], i);
                x0 += ri * wv[i][0];
                x1 += ri * wv[i][1];
                x2 += ri * wv[i][2];
                x3 += ri * wv[i][3];
            }
            float u0 = silu_f(x0), u1 = silu_f(x1), u2 = silu_f(x2), u3 = silu_f(x3);
#pragma unroll
            for (int d = 0; d < 3; d++)
                pacc[g][d] += u0 * w2[0][d] + u1 * w2[1][d] + u2 * w2[2][d] +
                              u3 * w2[3][d];
        }
    }
#pragma unroll
    for (int g = 0; g < 8; g++) {
        float p0 = pacc[g][0], p1 = pacc[g][1], p2 = pacc[g][2];
#pragma unroll
        for (int o = 16; o; o >>= 1) {
            p0 += __shfl_xor_sync(0xffffffffu, p0, o);
            p1 += __shfl_xor_sync(0xffffffffu, p1, o);
            p2 += __shfl_xor_sync(0xffffffffu, p2, o);
        }
        if (lane == 0 && e0 + g < E) {
            g_cvs[(size_t)(e0 + g) * 3 + 0] = p0;
            g_cvs[(size_t)(e0 + g) * 3 + 1] = p1;
            g_cvs[(size_t)(e0 + g) * 3 + 2] = p2;
        }
    }
}

// ---------------- row kernel: softmax + agg + finalize ------------------------
__global__ __launch_bounds__(256) void row_kernel(
    const float* __restrict__ h, const float* __restrict__ coord,
    float* __restrict__ out, float* __restrict__ alpha_out, int N) {
    __shared__ float wvr_s[9 * H];
    int tid = threadIdx.x, lane = tid & 31, w = tid >> 5;
    for (int i = tid; i < 9 * H; i += 256) wvr_s[i] = g_wvr[i];
    __syncthreads();
    int r = blockIdx.x * 8 + w;
    if (r >= N) return;
    int s = g_off[r], e = g_off[r + 1];

    float4 acc = make_float4(0.f, 0.f, 0.f, 0.f);
    float aS = 0.f, cg = 0.f;
    if (e > s) {
        float m = -1e30f;
        for (int p = s + lane; p < e; p += 32) m = fmaxf(m, g_araw[p]);
#pragma unroll
        for (int o = 16; o; o >>= 1)
            m = fmaxf(m, __shfl_xor_sync(0xffffffffu, m, o));
        float den = 0.f;
        for (int p = s + lane; p < e; p += 32) den += __expf(g_araw[p] - m);
#pragma unroll
        for (int o = 16; o; o >>= 1) den += __shfl_xor_sync(0xffffffffu, den, o);
        float invd = 1.f / den;

        int c3 = lane / 3;
        for (int p = s; p < e; p++) {
            float a = __expf(g_araw[p] - m) * invd;
            int c = g_cols[p];
            float4 hv = *(const float4*)&g_hv[(size_t)c * H + lane * 4];
            acc.x += a * hv.x;
            acc.y += a * hv.y;
            acc.z += a * hv.z;
            acc.w += a * hv.w;
            if (lane < 9) {
                aS += a * g_rads[(size_t)p * 9 + lane];
                cg += g_cds[(size_t)p * 9 + lane] * (a * g_cvs[(size_t)p * 3 + c3]);
            }
            if (lane == 0) alpha_out[g_perm[p]] = a;
        }
#pragma unroll
        for (int i = 0; i < 9; i++) {
            float asi = __shfl_sync(0xffffffffu, aS, i);
            acc.x += asi * wvr_s[i * H + lane * 4 + 0];
            acc.y += asi * wvr_s[i * H + lane * 4 + 1];
            acc.z += asi * wvr_s[i * H + lane * 4 + 2];
            acc.w += asi * wvr_s[i * H + lane * 4 + 3];
        }
    }
    float4 hh = *(const float4*)&h[(size_t)r * H + lane * 4];
    float4 o4 = make_float4(hh.x + acc.x, hh.y + acc.y, hh.z + acc.z, hh.w + acc.w);
    *(float4*)&out[(size_t)r * H + lane * 4] = o4;
    if (lane < 9) {
        float cgc = fminf(fmaxf(cg, -10.f), 10.f);
        out[(size_t)N * H + (size_t)r * 9 + lane] = coord[(size_t)r * 9 + lane] + cgc;
    }
}

// ---------------- launch -------------------------------------------------------
extern "C" void kernel_launch(void* const* d_in, const int* in_sizes, int n_in,
                              void* d_out, int out_size) {
    const float* h = (const float*)d_in[0];
    const float* coord = (const float*)d_in[1];
    const int* row = (const int*)d_in[2];
    const int* col = (const int*)d_in[3];
    const float* Wq = (const float*)d_in[4];
    const float* bq = (const float*)d_in[5];
    const float* Wkv = (const float*)d_in[6];
    const float* bkv = (const float*)d_in[7];
    const float* Wc1 = (const float*)d_in[8];
    const float* Wc2 = (const float*)d_in[9];
    int N = in_sizes[0] / H;
    int E = in_sizes[2];
    float* out = (float*)d_out;
    float* alpha_out = out + (size_t)N * H + (size_t)N * 9;

    size_t smem_g = (size_t)(128 * GPAD + 32 * GPAD) * sizeof(float);
    size_t smem_z = (size_t)2 * 128 * BSTRIDE * sizeof(unsigned short);
    cudaFuncSetAttribute((const void*)node_gemm_all,
                         cudaFuncAttributeMaxDynamicSharedMemorySize, (int)smem_g);
    cudaFuncSetAttribute((const void*)zgemm_kernel,
                         cudaFuncAttributeMaxDynamicSharedMemorySize, (int)smem_z);

    // CSR build
    zero_kernel<<<(N + 255) / 256, 256>>>(N);
    hist_kernel<<<(E + 255) / 256, 256>>>(row, E);
    scan_kernel<<<1, 1024>>>(N);
    scatter_kernel<<<(E + 255) / 256, 256>>>(row, col, E);

    // weight folds
    fold1_kernel<<<(H * H + 255) / 256, 256>>>(Wkv, bkv);
    fold2_kernel<<<(138 * ZDIM + 255) / 256, 256>>>(Wc1);

    // node GEMMs
    dim3 gall((N + 127) / 128, 3);
    node_gemm_all<<<gall, 256, smem_g>>>(h, Wq, bq, N);
    dim3 gz((N + 127) / 128, 4);
    zgemm_kernel<<<gz, 256, smem_z>>>(h, N);

    p_kernel<<<(N * 32 + 255) / 256, 256>>>(N);
    edge_prep_kernel<<<(E * 32 + 255) / 256, 256>>>(coord, E);
    cv_kernel<<<((E + 7) / 8 * 32 + 255) / 256, 256>>>(Wc2, E);
    row_kernel<<<(N + 7) / 8, 256>>>(h, coord, out, alpha_out, N);
}